// round 5
// baseline (speedup 1.0000x reference)
#include <cuda_runtime.h>
#include <cuda_bf16.h>
#include <math.h>

// ---------------------------------------------------------------------------
// SwinTransformerBlock (B=2, H=W=256, C=192, HID=768, heads=6, ws=8, shift=4)
// fp32 v3.1: packed-f32x2 GEMMs, register double-buffering (1 BAR/K-tile),
// 16B-aligned smem (LDS.64/128 safety), fused attention, LCE convs.
// ---------------------------------------------------------------------------

#define BATCH   2
#define HH      256
#define WW_     256
#define CC      192
#define HID     768
#define NHEAD   6
#define HD      32
#define WS      8
#define NTOK    64          // ws*ws
#define LTOT    (HH*WW_)    // 65536
#define MROWS   (BATCH*LTOT) // 131072
#define RCH     24          // C/RED

// -------------------- scratch (device globals, no allocation) --------------
__device__ float g_xn  [(size_t)MROWS*CC];
__device__ float g_qkv [(size_t)MROWS*3*CC];
__device__ float g_attn[(size_t)MROWS*CC];
__device__ float g_x1  [(size_t)MROWS*CC];
__device__ float g_ln2 [(size_t)MROWS*CC];
__device__ float g_h   [(size_t)MROWS*HID];
__device__ float g_y1  [(size_t)MROWS*RCH];
__device__ float g_y2  [(size_t)MROWS*RCH];
__device__ float g_y3  [(size_t)MROWS*CC];
__device__ float g_pool[BATCH*CC];
__device__ float g_gate[BATCH*CC];

// --------------------------- packed f32x2 helpers ---------------------------
typedef unsigned long long u64t;

__device__ __forceinline__ u64t fma2(u64t a, u64t b, u64t c) {
#if __CUDA_ARCH__ >= 1000
    u64t d;
    asm("fma.rn.f32x2 %0, %1, %2, %3;" : "=l"(d) : "l"(a), "l"(b), "l"(c));
    return d;
#else
    float alo=__uint_as_float((unsigned)a),   ahi=__uint_as_float((unsigned)(a>>32));
    float blo=__uint_as_float((unsigned)b),   bhi=__uint_as_float((unsigned)(b>>32));
    float clo=__uint_as_float((unsigned)c),   chi=__uint_as_float((unsigned)(c>>32));
    float lo=fmaf(alo,blo,clo), hi=fmaf(ahi,bhi,chi);
    return ((u64t)__float_as_uint(hi)<<32) | __float_as_uint(lo);
#endif
}
__device__ __forceinline__ u64t bcast2(float x) {
    u64t d;
    asm("mov.b64 %0, {%1, %1};" : "=l"(d) : "f"(x));
    return d;
}
__device__ __forceinline__ void unpack2(u64t p, float& lo, float& hi) {
    asm("mov.b64 {%0, %1}, %2;" : "=f"(lo), "=f"(hi) : "l"(p));
}

// -------------------------------- LayerNorm --------------------------------
__global__ void ln_kernel(const float* __restrict__ x, const float* __restrict__ g,
                          const float* __restrict__ b, float* __restrict__ o)
{
    int row  = blockIdx.x * 4 + threadIdx.y;
    int lane = threadIdx.x;
    const float* xr = x + (size_t)row * CC;
    float v[6];
    float s = 0.f;
#pragma unroll
    for (int k = 0; k < 6; k++) { v[k] = xr[lane + k*32]; s += v[k]; }
#pragma unroll
    for (int off = 16; off > 0; off >>= 1) s += __shfl_xor_sync(~0u, s, off);
    float mean = s * (1.f/192.f);
    float q = 0.f;
#pragma unroll
    for (int k = 0; k < 6; k++) { float d = v[k]-mean; q += d*d; }
#pragma unroll
    for (int off = 16; off > 0; off >>= 1) q += __shfl_xor_sync(~0u, q, off);
    float rs = rsqrtf(q * (1.f/192.f) + 1e-5f);
    float* orow = o + (size_t)row * CC;
#pragma unroll
    for (int k = 0; k < 6; k++) {
        int c = lane + k*32;
        orow[c] = (v[k]-mean)*rs*g[c] + b[c];
    }
}

// ------------------------- tiled fp32 GEMM: out = X @ W^T + epilogue -------
// X: (M,K) row-major,  W: (N,K) row-major.  BM=128 BN=64 BK=16, 256 thr.
// Register double-buffered (1 __syncthreads per K-tile), packed f32x2 over
// contiguous m-pairs.
// EPI 0: +bias | 1: +bias+res1 | 2: gelu(+bias) | 3: +bias+res1+res2*gate
__device__ __forceinline__ float gelu_exact(float x) {
    return 0.5f * x * (1.f + erff(x * 0.70710678118654752f));
}

template<int EPI>
__global__ void __launch_bounds__(256)
gemm_k(const float* __restrict__ X, const float* __restrict__ W,
       const float* __restrict__ bias, float* __restrict__ out,
       int M, int N, int K,
       const float* __restrict__ res1, const float* __restrict__ res2,
       const float* __restrict__ gate)
{
    __shared__ __align__(16) float Xs [2][16][132];  // [buf][k][m], 528B k-stride
    __shared__ __align__(16) float Wss[2][16][64];   // [buf][k][n]
    int bm = blockIdx.y << 7;
    int bn = blockIdx.x << 6;
    int t  = threadIdx.x;
    int tx = t & 15, ty = t >> 4;
    int m0 = ty << 3;                   // 8 contiguous rows per thread

    // gmem addressing for the cooperative tile loads
    int lmA0 = t >> 2;                  // X row within tile (chunk 0)
    int lmA1 = (256 + t) >> 2;          // X row within tile (chunk 1)
    int lk4  = (t & 3) << 2;            // k offset of float4
    int lnW  = t >> 2;                  // W row within tile
    const float* Xg0 = X + (size_t)(bm + lmA0) * K + lk4;
    const float* Xg1 = X + (size_t)(bm + lmA1) * K + lk4;
    const float* Wg  = W + (size_t)(bn + lnW ) * K + lk4;

    u64t acc[4][4];
#pragma unroll
    for (int i = 0; i < 4; i++)
#pragma unroll
        for (int j = 0; j < 4; j++) acc[i][j] = 0ull;

    int nt = K >> 4;

    // ---- prologue: tile 0 ----
    float4 rX0 = *reinterpret_cast<const float4*>(Xg0);
    float4 rX1 = *reinterpret_cast<const float4*>(Xg1);
    float4 rW  = *reinterpret_cast<const float4*>(Wg);
    {
        float* xd0 = &Xs[0][lk4][lmA0];
        xd0[0*132]=rX0.x; xd0[1*132]=rX0.y; xd0[2*132]=rX0.z; xd0[3*132]=rX0.w;
        float* xd1 = &Xs[0][lk4][lmA1];
        xd1[0*132]=rX1.x; xd1[1*132]=rX1.y; xd1[2*132]=rX1.z; xd1[3*132]=rX1.w;
        float* wd = &Wss[0][lk4][lnW];
        wd[0*64]=rW.x; wd[1*64]=rW.y; wd[2*64]=rW.z; wd[3*64]=rW.w;
    }
    __syncthreads();

    for (int i = 0; i < nt; i++) {
        int cb = i & 1;
        if (i + 1 < nt) {               // prefetch next tile into registers
            int off = (i + 1) << 4;
            rX0 = *reinterpret_cast<const float4*>(Xg0 + off);
            rX1 = *reinterpret_cast<const float4*>(Xg1 + off);
            rW  = *reinterpret_cast<const float4*>(Wg  + off);
        }
#pragma unroll
        for (int k = 0; k < 16; k++) {
            float4 bv = reinterpret_cast<float4*>(&Wss[cb][k][0])[tx];
            u64t bb[4] = { bcast2(bv.x), bcast2(bv.y), bcast2(bv.z), bcast2(bv.w) };
            const u64t* Xp = reinterpret_cast<const u64t*>(&Xs[cb][k][m0]);
            u64t pa[4] = { Xp[0], Xp[1], Xp[2], Xp[3] };
#pragma unroll
            for (int ii = 0; ii < 4; ii++)
#pragma unroll
                for (int jj = 0; jj < 4; jj++)
                    acc[ii][jj] = fma2(pa[ii], bb[jj], acc[ii][jj]);
        }
        if (i + 1 < nt) {               // stage next tile, single barrier
            int nb = cb ^ 1;
            float* xd0 = &Xs[nb][lk4][lmA0];
            xd0[0*132]=rX0.x; xd0[1*132]=rX0.y; xd0[2*132]=rX0.z; xd0[3*132]=rX0.w;
            float* xd1 = &Xs[nb][lk4][lmA1];
            xd1[0*132]=rX1.x; xd1[1*132]=rX1.y; xd1[2*132]=rX1.z; xd1[3*132]=rX1.w;
            float* wd = &Wss[nb][lk4][lnW];
            wd[0*64]=rW.x; wd[1*64]=rW.y; wd[2*64]=rW.z; wd[3*64]=rW.w;
            __syncthreads();
        }
    }

    int n0 = bn + (tx << 2);
#pragma unroll
    for (int i = 0; i < 4; i++) {
        float lo[4], hi[4];
#pragma unroll
        for (int j = 0; j < 4; j++) unpack2(acc[i][j], lo[j], hi[j]);
#pragma unroll
        for (int half = 0; half < 2; half++) {
            int m = bm + m0 + i*2 + half;
            size_t rowo = (size_t)m * N;
            float v[4];
#pragma unroll
            for (int j = 0; j < 4; j++) {
                float a = (half ? hi[j] : lo[j]) + __ldg(bias + n0 + j);
                if (EPI == 1) a += res1[rowo + n0 + j];
                if (EPI == 2) a = gelu_exact(a);
                if (EPI == 3) a += res1[rowo + n0 + j]
                                + res2[rowo + n0 + j] * gate[((m >> 16) * CC) + n0 + j];
                v[j] = a;
            }
            *reinterpret_cast<float4*>(out + rowo + n0) =
                make_float4(v[0], v[1], v[2], v[3]);
        }
    }
}

// ------------------------------- Attention ---------------------------------
// One block per (batch, window). Shift folded into gather/scatter indices:
// tokens addressed at window coords hs (mask regions keyed on hs, matching
// calculate_mask), data gathered/scattered at original coords (hs+4)&255.
__global__ void __launch_bounds__(256)
attn_kernel(const float* __restrict__ qkv, const float* __restrict__ rpb,
            float* __restrict__ out)
{
    __shared__ float qs[NTOK][33], ks[NTOK][33], vs[NTOK][33];
    __shared__ float S[NTOK][65];
    __shared__ int   rowi[NTOK];
    __shared__ int   regn[NTOK];

    int t   = threadIdx.x;
    int blk = blockIdx.x;
    int b   = blk >> 10;
    int wh  = (blk >> 5) & 31;
    int ww  = blk & 31;

    if (t < NTOK) {
        int i  = t >> 3, j = t & 7;
        int ha = wh*WS + i, wa = ww*WS + j;   // window (shifted-frame) coords
        rowi[t] = b*LTOT + ((ha+4)&255)*WW_ + ((wa+4)&255);
        int rh = (ha < 248) ? 0 : (ha < 252 ? 1 : 2);
        int rw = (wa < 248) ? 0 : (wa < 252 ? 1 : 2);
        regn[t] = rh*3 + rw;
    }
    __syncthreads();

    const float scale = 0.17677669529663687f; // 1/sqrt(32)

    for (int h = 0; h < NHEAD; h++) {
        {
            int tok  = t >> 2, part = t & 3;
            size_t base = (size_t)rowi[tok]*(3*CC) + h*HD + part*8;
            float4 q0 = *reinterpret_cast<const float4*>(qkv + base);
            float4 q1 = *reinterpret_cast<const float4*>(qkv + base + 4);
            float4 k0 = *reinterpret_cast<const float4*>(qkv + base + CC);
            float4 k1 = *reinterpret_cast<const float4*>(qkv + base + CC + 4);
            float4 v0 = *reinterpret_cast<const float4*>(qkv + base + 2*CC);
            float4 v1 = *reinterpret_cast<const float4*>(qkv + base + 2*CC + 4);
            int d = part*8;
            qs[tok][d+0]=q0.x; qs[tok][d+1]=q0.y; qs[tok][d+2]=q0.z; qs[tok][d+3]=q0.w;
            qs[tok][d+4]=q1.x; qs[tok][d+5]=q1.y; qs[tok][d+6]=q1.z; qs[tok][d+7]=q1.w;
            ks[tok][d+0]=k0.x; ks[tok][d+1]=k0.y; ks[tok][d+2]=k0.z; ks[tok][d+3]=k0.w;
            ks[tok][d+4]=k1.x; ks[tok][d+5]=k1.y; ks[tok][d+6]=k1.z; ks[tok][d+7]=k1.w;
            vs[tok][d+0]=v0.x; vs[tok][d+1]=v0.y; vs[tok][d+2]=v0.z; vs[tok][d+3]=v0.w;
            vs[tok][d+4]=v1.x; vs[tok][d+5]=v1.y; vs[tok][d+6]=v1.z; vs[tok][d+7]=v1.w;
        }
        __syncthreads();

        {
            int i0 = (t >> 4) << 2;
            int j0 = (t & 15) << 2;
            float sacc[4][4] = {};
#pragma unroll
            for (int d = 0; d < HD; d++) {
                float a[4], bb[4];
#pragma unroll
                for (int ii = 0; ii < 4; ii++) a[ii]  = qs[i0+ii][d];
#pragma unroll
                for (int jj = 0; jj < 4; jj++) bb[jj] = ks[j0+jj][d];
#pragma unroll
                for (int ii = 0; ii < 4; ii++)
#pragma unroll
                    for (int jj = 0; jj < 4; jj++)
                        sacc[ii][jj] += a[ii]*bb[jj];
            }
#pragma unroll
            for (int ii = 0; ii < 4; ii++) {
#pragma unroll
                for (int jj = 0; jj < 4; jj++) {
                    int i = i0+ii, j = j0+jj;
                    int rel = ((i>>3)-(j>>3)+7)*15 + ((i&7)-(j&7)+7);
                    float bias = __ldg(rpb + rel*NHEAD + h);
                    float mv   = (regn[i] == regn[j]) ? 0.f : -100.f;
                    S[i][j] = sacc[ii][jj]*scale + bias + mv;
                }
            }
        }
        __syncthreads();

        {
            int ri = t >> 2;
            int c0 = (t & 3) << 4;
            float mx = -1e30f;
#pragma unroll
            for (int cc = 0; cc < 16; cc++) mx = fmaxf(mx, S[ri][c0+cc]);
            mx = fmaxf(mx, __shfl_xor_sync(~0u, mx, 1));
            mx = fmaxf(mx, __shfl_xor_sync(~0u, mx, 2));
            float ev[16];
            float sum = 0.f;
#pragma unroll
            for (int cc = 0; cc < 16; cc++) {
                ev[cc] = __expf(S[ri][c0+cc] - mx);
                sum += ev[cc];
            }
            sum += __shfl_xor_sync(~0u, sum, 1);
            sum += __shfl_xor_sync(~0u, sum, 2);
            float inv = 1.f / sum;
#pragma unroll
            for (int cc = 0; cc < 16; cc++) S[ri][c0+cc] = ev[cc]*inv;
        }
        __syncthreads();

        {
            int r0 = (t >> 3) << 1;
            int d0 = (t & 7) << 2;
            float o0[4] = {}, o1[4] = {};
#pragma unroll
            for (int j = 0; j < NTOK; j++) {
                float p0 = S[r0][j], p1 = S[r0+1][j];
#pragma unroll
                for (int dd = 0; dd < 4; dd++) {
                    float vv = vs[j][d0+dd];
                    o0[dd] += p0*vv;
                    o1[dd] += p1*vv;
                }
            }
            size_t ob0 = (size_t)rowi[r0  ]*CC + h*HD + d0;
            size_t ob1 = (size_t)rowi[r0+1]*CC + h*HD + d0;
            *reinterpret_cast<float4*>(out + ob0) = make_float4(o0[0],o0[1],o0[2],o0[3]);
            *reinterpret_cast<float4*>(out + ob1) = make_float4(o1[0],o1[1],o1[2],o1[3]);
        }
        __syncthreads();
    }
}

// ------------------------------ LCE conv 1x1 (192->24) ---------------------
__global__ void __launch_bounds__(128)
conv1_k(const float* __restrict__ xin, const float* __restrict__ w,
        const float* __restrict__ bias, float* __restrict__ y)
{
    __shared__ float Xs[32][193];
    __shared__ float Ws[RCH*CC];
    int t = threadIdx.x;
    size_t p0 = (size_t)blockIdx.x * 32;

    for (int e = t; e < RCH*CC; e += 128) Ws[e] = w[e];
    for (int e = t; e < 32*CC; e += 128) {
        int p = e / CC, c = e % CC;
        Xs[p][c] = xin[(p0+p)*CC + c];
    }
    __syncthreads();

    int pp = (t & 15) * 2;
    int cg = (t >> 4) * 3;
    float a0[3] = {}, a1[3] = {};
    for (int k = 0; k < CC; k++) {
        float x0 = Xs[pp][k], x1 = Xs[pp+1][k];
#pragma unroll
        for (int j = 0; j < 3; j++) {
            float wv = Ws[(cg+j)*CC + k];
            a0[j] += x0*wv; a1[j] += x1*wv;
        }
    }
#pragma unroll
    for (int j = 0; j < 3; j++) {
        int c = cg+j;
        y[(p0+pp  )*RCH + c] = a0[j] + bias[c];
        y[(p0+pp+1)*RCH + c] = a1[j] + bias[c];
    }
}

// ------------------------------ LCE conv 3x3 (24->24, pad 1) ----------------
__global__ void __launch_bounds__(256)
conv2_k(const float* __restrict__ y1, const float* __restrict__ w,
        const float* __restrict__ bias, float* __restrict__ y2)
{
    __shared__ float Ins[10][18][25];
    __shared__ float Ws2[RCH*RCH*9];
    int t  = threadIdx.x;
    int b  = blockIdx.z;
    int h0 = blockIdx.y * 8;
    int w0 = blockIdx.x * 16;

    for (int e = t; e < RCH*RCH*9; e += 256) Ws2[e] = w[e];
    for (int e = t; e < 10*18*RCH; e += 256) {
        int ci  = e % RCH;
        int col = (e / RCH) % 18;
        int row = e / (RCH*18);
        int hh  = h0 + row - 1, wc = w0 + col - 1;
        float v = 0.f;
        if (hh >= 0 && hh < HH && wc >= 0 && wc < WW_)
            v = y1[(((size_t)b*HH + hh)*WW_ + wc)*RCH + ci];
        Ins[row][col][ci] = v;
    }
    __syncthreads();

    int pg  = t & 31;
    int py  = pg >> 2;
    int px0 = (pg & 3) << 2;
    int cg  = (t >> 5) * 3;
    float acc[4][3] = {};
#pragma unroll
    for (int kh = 0; kh < 3; kh++) {
#pragma unroll
        for (int kw = 0; kw < 3; kw++) {
            for (int ci = 0; ci < RCH; ci++) {
                float xv[4];
#pragma unroll
                for (int q = 0; q < 4; q++) xv[q] = Ins[py+kh][px0+q+kw][ci];
#pragma unroll
                for (int j = 0; j < 3; j++) {
                    float wv = Ws2[((cg+j)*RCH + ci)*9 + kh*3 + kw];
#pragma unroll
                    for (int q = 0; q < 4; q++) acc[q][j] += xv[q]*wv;
                }
            }
        }
    }
#pragma unroll
    for (int q = 0; q < 4; q++)
#pragma unroll
        for (int j = 0; j < 3; j++)
            y2[(((size_t)b*HH + h0+py)*WW_ + w0+px0+q)*RCH + cg+j]
                = acc[q][j] + bias[cg+j];
}

// ----------------- LCE conv 1x1 (24->192) + LeakyReLU + pool ----------------
__global__ void __launch_bounds__(256)
conv3_k(const float* __restrict__ y2, const float* __restrict__ w,
        const float* __restrict__ bias, float* __restrict__ y3,
        float* __restrict__ pool)
{
    __shared__ float Xs[32][25];
    __shared__ float Ws[CC*RCH];
    __shared__ float psum[CC];
    int t = threadIdx.x;
    size_t p0 = (size_t)blockIdx.x * 32;
    int b = (int)(p0 >> 16);

    for (int e = t; e < CC*RCH; e += 256) Ws[e] = w[e];
    for (int e = t; e < 32*RCH; e += 256) Xs[e/RCH][e%RCH] = y2[p0*RCH + e];
    if (t < CC) psum[t] = 0.f;
    __syncthreads();

    int pp = (t & 15) * 2;
    int cg = (t >> 4) * 12;
    float a0[12] = {}, a1[12] = {};
    for (int k = 0; k < RCH; k++) {
        float x0 = Xs[pp][k], x1 = Xs[pp+1][k];
#pragma unroll
        for (int j = 0; j < 12; j++) {
            float wv = Ws[(cg+j)*RCH + k];
            a0[j] += x0*wv; a1[j] += x1*wv;
        }
    }
#pragma unroll
    for (int j = 0; j < 12; j++) {
        int c = cg + j;
        float v0 = a0[j] + bias[c]; v0 = (v0 >= 0.f) ? v0 : 0.2f*v0;
        float v1 = a1[j] + bias[c]; v1 = (v1 >= 0.f) ? v1 : 0.2f*v1;
        y3[(p0+pp  )*CC + c] = v0;
        y3[(p0+pp+1)*CC + c] = v1;
        float v = v0 + v1;
        v += __shfl_xor_sync(~0u, v, 1);
        v += __shfl_xor_sync(~0u, v, 2);
        v += __shfl_xor_sync(~0u, v, 4);
        v += __shfl_xor_sync(~0u, v, 8);
        if ((t & 15) == 0) atomicAdd(&psum[c], v);
    }
    __syncthreads();
    if (t < CC) atomicAdd(&pool[b*CC + t], psum[t]);
}

// ------------------------------ SE gate ------------------------------------
__global__ void zero_pool_k(float* pool) { pool[threadIdx.x] = 0.f; }

__global__ void __launch_bounds__(192)
se_kernel(const float* __restrict__ pool, const float* __restrict__ fc1w,
          const float* __restrict__ fc2w, float* __restrict__ gate)
{
    __shared__ float ssh[CC];
    __shared__ float t1[RCH];
    int b = blockIdx.x;
    int t = threadIdx.x;
    ssh[t] = pool[b*CC + t] * (1.f / (float)LTOT);
    __syncthreads();
    if (t < RCH) {
        float a = 0.f;
        for (int c = 0; c < CC; c++) a += ssh[c]*fc1w[t*CC + c];
        t1[t] = fmaxf(a, 0.f);
    }
    __syncthreads();
    float a = 0.f;
#pragma unroll
    for (int j = 0; j < RCH; j++) a += t1[j]*fc2w[t*RCH + j];
    gate[b*CC + t] = 1.f / (1.f + __expf(-a));
}

// ------------------------------ launcher -----------------------------------
extern "C" void kernel_launch(void* const* d_in, const int* in_sizes, int n_in,
                              void* d_out, int out_size)
{
    const float* x       = (const float*)d_in[0];
    const float* n1g     = (const float*)d_in[1];
    const float* n1b     = (const float*)d_in[2];
    const float* qkv_w   = (const float*)d_in[3];
    const float* qkv_b   = (const float*)d_in[4];
    const float* rpb     = (const float*)d_in[5];
    const float* proj_w  = (const float*)d_in[6];
    const float* proj_b  = (const float*)d_in[7];
    const float* n2g     = (const float*)d_in[8];
    const float* n2b     = (const float*)d_in[9];
    const float* fc1_w   = (const float*)d_in[10];
    const float* fc1_b   = (const float*)d_in[11];
    const float* fc2_w   = (const float*)d_in[12];
    const float* fc2_b   = (const float*)d_in[13];
    const float* c1_w    = (const float*)d_in[14];
    const float* c1_b    = (const float*)d_in[15];
    const float* c2_w    = (const float*)d_in[16];
    const float* c2_b    = (const float*)d_in[17];
    const float* c3_w    = (const float*)d_in[18];
    const float* c3_b    = (const float*)d_in[19];
    const float* sefc1   = (const float*)d_in[20];
    const float* sefc2   = (const float*)d_in[21];
    float* out = (float*)d_out;

    float *xn, *qkv, *attn, *x1, *ln2, *hbuf, *y1, *y2, *y3, *pool, *gate;
    cudaGetSymbolAddress((void**)&xn,   g_xn);
    cudaGetSymbolAddress((void**)&qkv,  g_qkv);
    cudaGetSymbolAddress((void**)&attn, g_attn);
    cudaGetSymbolAddress((void**)&x1,   g_x1);
    cudaGetSymbolAddress((void**)&ln2,  g_ln2);
    cudaGetSymbolAddress((void**)&hbuf, g_h);
    cudaGetSymbolAddress((void**)&y1,   g_y1);
    cudaGetSymbolAddress((void**)&y2,   g_y2);
    cudaGetSymbolAddress((void**)&y3,   g_y3);
    cudaGetSymbolAddress((void**)&pool, g_pool);
    cudaGetSymbolAddress((void**)&gate, g_gate);

    // 1. LN1 -> xn
    ln_kernel<<<MROWS/4, dim3(32,4)>>>(x, n1g, n1b, xn);

    // 2. qkv GEMM: (131072 x 576) = xn @ qkv_w^T + b
    gemm_k<0><<<dim3(576/64, MROWS/128), 256>>>(xn, qkv_w, qkv_b, qkv,
        MROWS, 3*CC, CC, nullptr, nullptr, nullptr);

    // 3. window attention (shift folded into gather/scatter)
    attn_kernel<<<BATCH*1024, 256>>>(qkv, rpb, attn);

    // 4. proj GEMM + residual(x) -> x1
    gemm_k<1><<<dim3(CC/64, MROWS/128), 256>>>(attn, proj_w, proj_b, x1,
        MROWS, CC, CC, x, nullptr, nullptr);

    // 5. LN2 -> ln2
    ln_kernel<<<MROWS/4, dim3(32,4)>>>(x1, n2g, n2b, ln2);

    // 6. fc1 GEMM + exact GELU -> hbuf
    gemm_k<2><<<dim3(HID/64, MROWS/128), 256>>>(ln2, fc1_w, fc1_b, hbuf,
        MROWS, HID, CC, nullptr, nullptr, nullptr);

    // 7-10. LCE branch on xn
    conv1_k<<<MROWS/32, 128>>>(xn, c1_w, c1_b, y1);
    conv2_k<<<dim3(WW_/16, HH/8, BATCH), 256>>>(y1, c2_w, c2_b, y2);
    zero_pool_k<<<1, BATCH*CC>>>(pool);
    conv3_k<<<MROWS/32, 256>>>(y2, c3_w, c3_b, y3, pool);
    se_kernel<<<BATCH, CC>>>(pool, sefc1, sefc2, gate);

    // 11. fc2 GEMM + x1 + y3*gate -> d_out
    gemm_k<3><<<dim3(CC/64, MROWS/128), 256>>>(hbuf, fc2_w, fc2_b, out,
        MROWS, CC, HID, x1, y3, gate);
}

// round 7
// speedup vs baseline: 1.3624x; 1.3624x over previous
#include <cuda_runtime.h>
#include <cuda_bf16.h>
#include <math.h>

// ---------------------------------------------------------------------------
// SwinTransformerBlock (B=2, H=W=256, C=192, HID=768, heads=6, ws=8, shift=4)
// v4: tf32 mma.sync tensor-core GEMMs (fp32 accum), double-buffered staging;
// fp32 fused window attention + LN + LCE convs unchanged from v3.1.
// ---------------------------------------------------------------------------

#define BATCH   2
#define HH      256
#define WW_     256
#define CC      192
#define HID     768
#define NHEAD   6
#define HD      32
#define WS      8
#define NTOK    64          // ws*ws
#define LTOT    (HH*WW_)    // 65536
#define MROWS   (BATCH*LTOT) // 131072
#define RCH     24          // C/RED

// -------------------- scratch (device globals, no allocation) --------------
__device__ float g_xn  [(size_t)MROWS*CC];
__device__ float g_qkv [(size_t)MROWS*3*CC];
__device__ float g_attn[(size_t)MROWS*CC];
__device__ float g_x1  [(size_t)MROWS*CC];
__device__ float g_ln2 [(size_t)MROWS*CC];
__device__ float g_h   [(size_t)MROWS*HID];
__device__ float g_y1  [(size_t)MROWS*RCH];
__device__ float g_y2  [(size_t)MROWS*RCH];
__device__ float g_y3  [(size_t)MROWS*CC];
__device__ float g_pool[BATCH*CC];
__device__ float g_gate[BATCH*CC];

// ------------------------------ tf32 helpers --------------------------------
__device__ __forceinline__ unsigned f2tf(float f) {
    unsigned u;
    asm("cvt.rna.tf32.f32 %0, %1;" : "=r"(u) : "f"(f));
    return u;
}

// D(16x8,f32) += A(16x8,tf32,row) * B(8x8,tf32,col)
__device__ __forceinline__ void mma_tf32(float* c, const unsigned* a, const unsigned* b) {
    asm volatile(
        "mma.sync.aligned.m16n8k8.row.col.f32.tf32.tf32.f32 "
        "{%0,%1,%2,%3}, {%4,%5,%6,%7}, {%8,%9}, {%0,%1,%2,%3};\n"
        : "+f"(c[0]), "+f"(c[1]), "+f"(c[2]), "+f"(c[3])
        : "r"(a[0]), "r"(a[1]), "r"(a[2]), "r"(a[3]), "r"(b[0]), "r"(b[1]));
}

// -------------------------------- LayerNorm --------------------------------
__global__ void ln_kernel(const float* __restrict__ x, const float* __restrict__ g,
                          const float* __restrict__ b, float* __restrict__ o)
{
    int row  = blockIdx.x * 4 + threadIdx.y;
    int lane = threadIdx.x;
    const float* xr = x + (size_t)row * CC;
    float v[6];
    float s = 0.f;
#pragma unroll
    for (int k = 0; k < 6; k++) { v[k] = xr[lane + k*32]; s += v[k]; }
#pragma unroll
    for (int off = 16; off > 0; off >>= 1) s += __shfl_xor_sync(~0u, s, off);
    float mean = s * (1.f/192.f);
    float q = 0.f;
#pragma unroll
    for (int k = 0; k < 6; k++) { float d = v[k]-mean; q += d*d; }
#pragma unroll
    for (int off = 16; off > 0; off >>= 1) q += __shfl_xor_sync(~0u, q, off);
    float rs = rsqrtf(q * (1.f/192.f) + 1e-5f);
    float* orow = o + (size_t)row * CC;
#pragma unroll
    for (int k = 0; k < 6; k++) {
        int c = lane + k*32;
        orow[c] = (v[k]-mean)*rs*g[c] + b[c];
    }
}

// ------------------- tf32 tensor-core GEMM: out = X @ W^T -------------------
// X: (M,K) row-major, W: (N,K) row-major (= col-major KxN, matching mma .col).
// BM=128 BN=64 BK=16, 256 thr (8 warps), warp tile 32x32 = 2x4 m16n8k8 mmas.
// smem: As[m][k] stride 20, Bs[n][k] stride 20 (fragment loads conflict-free:
// banks (g*20+tig) mod 32 all distinct). fp32->tf32 once per element at stage.
// EPI 0: +bias | 1: +bias+res1 | 2: gelu(+bias) | 3: +bias+res1+res2*gate
__device__ __forceinline__ float gelu_exact(float x) {
    return 0.5f * x * (1.f + erff(x * 0.70710678118654752f));
}

template<int EPI>
__global__ void __launch_bounds__(256, 2)
gemm_tc(const float* __restrict__ X, const float* __restrict__ W,
        const float* __restrict__ bias, float* __restrict__ out,
        int M, int N, int K,
        const float* __restrict__ res1, const float* __restrict__ res2,
        const float* __restrict__ gate)
{
    __shared__ __align__(16) unsigned As[2][128][20];
    __shared__ __align__(16) unsigned Bs[2][64][20];

    int bm = blockIdx.y << 7;
    int bn = blockIdx.x << 6;
    int t    = threadIdx.x;
    int w    = t >> 5;
    int lane = t & 31;
    int g    = lane >> 2;       // groupID 0..7
    int tig  = lane & 3;        // thread-in-group 0..3
    int wm   = (w & 3) << 5;    // warp m offset: 0,32,64,96
    int wn   = (w >> 2) << 5;   // warp n offset: 0,32

    // cooperative staging addresses (same tile -> 2 A chunks + 1 B chunk)
    int sm0 = t >> 2;           // 0..63
    int sk4 = (t & 3) << 2;     // 0,4,8,12
    const float* Xg0 = X + (size_t)(bm + sm0)      * K + sk4;
    const float* Xg1 = X + (size_t)(bm + 64 + sm0) * K + sk4;
    const float* Wg  = W + (size_t)(bn + sm0)      * K + sk4;

    float acc[2][4][4];
#pragma unroll
    for (int i = 0; i < 2; i++)
#pragma unroll
        for (int j = 0; j < 4; j++)
#pragma unroll
            for (int q = 0; q < 4; q++) acc[i][j][q] = 0.f;

    int nt = K >> 4;

    // ---- prologue: stage tile 0 ----
    float4 rX0 = *reinterpret_cast<const float4*>(Xg0);
    float4 rX1 = *reinterpret_cast<const float4*>(Xg1);
    float4 rW  = *reinterpret_cast<const float4*>(Wg);
    *reinterpret_cast<uint4*>(&As[0][sm0][sk4]) =
        make_uint4(f2tf(rX0.x), f2tf(rX0.y), f2tf(rX0.z), f2tf(rX0.w));
    *reinterpret_cast<uint4*>(&As[0][64+sm0][sk4]) =
        make_uint4(f2tf(rX1.x), f2tf(rX1.y), f2tf(rX1.z), f2tf(rX1.w));
    *reinterpret_cast<uint4*>(&Bs[0][sm0][sk4]) =
        make_uint4(f2tf(rW.x), f2tf(rW.y), f2tf(rW.z), f2tf(rW.w));
    __syncthreads();

    for (int i = 0; i < nt; i++) {
        int cb = i & 1;
        if (i + 1 < nt) {           // prefetch next tile into registers
            int off = (i + 1) << 4;
            rX0 = *reinterpret_cast<const float4*>(Xg0 + off);
            rX1 = *reinterpret_cast<const float4*>(Xg1 + off);
            rW  = *reinterpret_cast<const float4*>(Wg  + off);
        }
#pragma unroll
        for (int s = 0; s < 2; s++) {
            int k0 = s << 3;
            unsigned a[2][4], b[4][2];
#pragma unroll
            for (int mi = 0; mi < 2; mi++) {
                int r0 = wm + (mi << 4) + g;
                a[mi][0] = As[cb][r0    ][k0 + tig];
                a[mi][1] = As[cb][r0 + 8][k0 + tig];
                a[mi][2] = As[cb][r0    ][k0 + tig + 4];
                a[mi][3] = As[cb][r0 + 8][k0 + tig + 4];
            }
#pragma unroll
            for (int ni = 0; ni < 4; ni++) {
                int c0 = wn + (ni << 3) + g;
                b[ni][0] = Bs[cb][c0][k0 + tig];
                b[ni][1] = Bs[cb][c0][k0 + tig + 4];
            }
#pragma unroll
            for (int mi = 0; mi < 2; mi++)
#pragma unroll
                for (int ni = 0; ni < 4; ni++)
                    mma_tf32(acc[mi][ni], a[mi], b[ni]);
        }
        if (i + 1 < nt) {           // stage next tile
            int nb = cb ^ 1;
            __syncthreads();        // ensure all reads of buf nb (i-1) done
            *reinterpret_cast<uint4*>(&As[nb][sm0][sk4]) =
                make_uint4(f2tf(rX0.x), f2tf(rX0.y), f2tf(rX0.z), f2tf(rX0.w));
            *reinterpret_cast<uint4*>(&As[nb][64+sm0][sk4]) =
                make_uint4(f2tf(rX1.x), f2tf(rX1.y), f2tf(rX1.z), f2tf(rX1.w));
            *reinterpret_cast<uint4*>(&Bs[nb][sm0][sk4]) =
                make_uint4(f2tf(rW.x), f2tf(rW.y), f2tf(rW.z), f2tf(rW.w));
            __syncthreads();
        }
    }

    // ---- epilogue ----
#pragma unroll
    for (int mi = 0; mi < 2; mi++) {
        int r0 = bm + wm + (mi << 4) + g;
        int r1 = r0 + 8;
        int batch = r0 >> 16;
#pragma unroll
        for (int ni = 0; ni < 4; ni++) {
            int c = bn + wn + (ni << 3) + (tig << 1);
            float b0 = __ldg(bias + c), b1 = __ldg(bias + c + 1);
            float v00 = acc[mi][ni][0] + b0, v01 = acc[mi][ni][1] + b1;
            float v10 = acc[mi][ni][2] + b0, v11 = acc[mi][ni][3] + b1;
            size_t o0 = (size_t)r0 * N + c;
            size_t o1 = (size_t)r1 * N + c;
            if (EPI == 1) {
                v00 += res1[o0]; v01 += res1[o0+1];
                v10 += res1[o1]; v11 += res1[o1+1];
            }
            if (EPI == 2) {
                v00 = gelu_exact(v00); v01 = gelu_exact(v01);
                v10 = gelu_exact(v10); v11 = gelu_exact(v11);
            }
            if (EPI == 3) {
                float g0 = gate[batch*CC + c], g1 = gate[batch*CC + c + 1];
                v00 += res1[o0]   + res2[o0]  *g0;
                v01 += res1[o0+1] + res2[o0+1]*g1;
                v10 += res1[o1]   + res2[o1]  *g0;
                v11 += res1[o1+1] + res2[o1+1]*g1;
            }
            *reinterpret_cast<float2*>(out + o0) = make_float2(v00, v01);
            *reinterpret_cast<float2*>(out + o1) = make_float2(v10, v11);
        }
    }
}

// ------------------------------- Attention ---------------------------------
// One block per (batch, window). Shift folded into gather/scatter indices:
// mask regions keyed on window coords (matching calculate_mask), data
// gathered/scattered at original coords (hs+4)&255.
__global__ void __launch_bounds__(256)
attn_kernel(const float* __restrict__ qkv, const float* __restrict__ rpb,
            float* __restrict__ out)
{
    __shared__ float qs[NTOK][33], ks[NTOK][33], vs[NTOK][33];
    __shared__ float S[NTOK][65];
    __shared__ int   rowi[NTOK];
    __shared__ int   regn[NTOK];

    int t   = threadIdx.x;
    int blk = blockIdx.x;
    int b   = blk >> 10;
    int wh  = (blk >> 5) & 31;
    int ww  = blk & 31;

    if (t < NTOK) {
        int i  = t >> 3, j = t & 7;
        int ha = wh*WS + i, wa = ww*WS + j;   // window (shifted-frame) coords
        rowi[t] = b*LTOT + ((ha+4)&255)*WW_ + ((wa+4)&255);
        int rh = (ha < 248) ? 0 : (ha < 252 ? 1 : 2);
        int rw = (wa < 248) ? 0 : (wa < 252 ? 1 : 2);
        regn[t] = rh*3 + rw;
    }
    __syncthreads();

    const float scale = 0.17677669529663687f; // 1/sqrt(32)

    for (int h = 0; h < NHEAD; h++) {
        {
            int tok  = t >> 2, part = t & 3;
            size_t base = (size_t)rowi[tok]*(3*CC) + h*HD + part*8;
            float4 q0 = *reinterpret_cast<const float4*>(qkv + base);
            float4 q1 = *reinterpret_cast<const float4*>(qkv + base + 4);
            float4 k0 = *reinterpret_cast<const float4*>(qkv + base + CC);
            float4 k1 = *reinterpret_cast<const float4*>(qkv + base + CC + 4);
            float4 v0 = *reinterpret_cast<const float4*>(qkv + base + 2*CC);
            float4 v1 = *reinterpret_cast<const float4*>(qkv + base + 2*CC + 4);
            int d = part*8;
            qs[tok][d+0]=q0.x; qs[tok][d+1]=q0.y; qs[tok][d+2]=q0.z; qs[tok][d+3]=q0.w;
            qs[tok][d+4]=q1.x; qs[tok][d+5]=q1.y; qs[tok][d+6]=q1.z; qs[tok][d+7]=q1.w;
            ks[tok][d+0]=k0.x; ks[tok][d+1]=k0.y; ks[tok][d+2]=k0.z; ks[tok][d+3]=k0.w;
            ks[tok][d+4]=k1.x; ks[tok][d+5]=k1.y; ks[tok][d+6]=k1.z; ks[tok][d+7]=k1.w;
            vs[tok][d+0]=v0.x; vs[tok][d+1]=v0.y; vs[tok][d+2]=v0.z; vs[tok][d+3]=v0.w;
            vs[tok][d+4]=v1.x; vs[tok][d+5]=v1.y; vs[tok][d+6]=v1.z; vs[tok][d+7]=v1.w;
        }
        __syncthreads();

        {
            int i0 = (t >> 4) << 2;
            int j0 = (t & 15) << 2;
            float sacc[4][4] = {};
#pragma unroll
            for (int d = 0; d < HD; d++) {
                float a[4], bb[4];
#pragma unroll
                for (int ii = 0; ii < 4; ii++) a[ii]  = qs[i0+ii][d];
#pragma unroll
                for (int jj = 0; jj < 4; jj++) bb[jj] = ks[j0+jj][d];
#pragma unroll
                for (int ii = 0; ii < 4; ii++)
#pragma unroll
                    for (int jj = 0; jj < 4; jj++)
                        sacc[ii][jj] += a[ii]*bb[jj];
            }
#pragma unroll
            for (int ii = 0; ii < 4; ii++) {
#pragma unroll
                for (int jj = 0; jj < 4; jj++) {
                    int i = i0+ii, j = j0+jj;
                    int rel = ((i>>3)-(j>>3)+7)*15 + ((i&7)-(j&7)+7);
                    float bias = __ldg(rpb + rel*NHEAD + h);
                    float mv   = (regn[i] == regn[j]) ? 0.f : -100.f;
                    S[i][j] = sacc[ii][jj]*scale + bias + mv;
                }
            }
        }
        __syncthreads();

        {
            int ri = t >> 2;
            int c0 = (t & 3) << 4;
            float mx = -1e30f;
#pragma unroll
            for (int cc = 0; cc < 16; cc++) mx = fmaxf(mx, S[ri][c0+cc]);
            mx = fmaxf(mx, __shfl_xor_sync(~0u, mx, 1));
            mx = fmaxf(mx, __shfl_xor_sync(~0u, mx, 2));
            float ev[16];
            float sum = 0.f;
#pragma unroll
            for (int cc = 0; cc < 16; cc++) {
                ev[cc] = __expf(S[ri][c0+cc] - mx);
                sum += ev[cc];
            }
            sum += __shfl_xor_sync(~0u, sum, 1);
            sum += __shfl_xor_sync(~0u, sum, 2);
            float inv = 1.f / sum;
#pragma unroll
            for (int cc = 0; cc < 16; cc++) S[ri][c0+cc] = ev[cc]*inv;
        }
        __syncthreads();

        {
            int r0 = (t >> 3) << 1;
            int d0 = (t & 7) << 2;
            float o0[4] = {}, o1[4] = {};
#pragma unroll
            for (int j = 0; j < NTOK; j++) {
                float p0 = S[r0][j], p1 = S[r0+1][j];
#pragma unroll
                for (int dd = 0; dd < 4; dd++) {
                    float vv = vs[j][d0+dd];
                    o0[dd] += p0*vv;
                    o1[dd] += p1*vv;
                }
            }
            size_t ob0 = (size_t)rowi[r0  ]*CC + h*HD + d0;
            size_t ob1 = (size_t)rowi[r0+1]*CC + h*HD + d0;
            *reinterpret_cast<float4*>(out + ob0) = make_float4(o0[0],o0[1],o0[2],o0[3]);
            *reinterpret_cast<float4*>(out + ob1) = make_float4(o1[0],o1[1],o1[2],o1[3]);
        }
        __syncthreads();
    }
}

// ------------------------------ LCE conv 1x1 (192->24) ---------------------
__global__ void __launch_bounds__(128)
conv1_k(const float* __restrict__ xin, const float* __restrict__ w,
        const float* __restrict__ bias, float* __restrict__ y)
{
    __shared__ float Xs[32][193];
    __shared__ float Ws[RCH*CC];
    int t = threadIdx.x;
    size_t p0 = (size_t)blockIdx.x * 32;

    for (int e = t; e < RCH*CC; e += 128) Ws[e] = w[e];
    for (int e = t; e < 32*CC; e += 128) {
        int p = e / CC, c = e % CC;
        Xs[p][c] = xin[(p0+p)*CC + c];
    }
    __syncthreads();

    int pp = (t & 15) * 2;
    int cg = (t >> 4) * 3;
    float a0[3] = {}, a1[3] = {};
    for (int k = 0; k < CC; k++) {
        float x0 = Xs[pp][k], x1 = Xs[pp+1][k];
#pragma unroll
        for (int j = 0; j < 3; j++) {
            float wv = Ws[(cg+j)*CC + k];
            a0[j] += x0*wv; a1[j] += x1*wv;
        }
    }
#pragma unroll
    for (int j = 0; j < 3; j++) {
        int c = cg+j;
        y[(p0+pp  )*RCH + c] = a0[j] + bias[c];
        y[(p0+pp+1)*RCH + c] = a1[j] + bias[c];
    }
}

// ------------------------------ LCE conv 3x3 (24->24, pad 1) ----------------
__global__ void __launch_bounds__(256)
conv2_k(const float* __restrict__ y1, const float* __restrict__ w,
        const float* __restrict__ bias, float* __restrict__ y2)
{
    __shared__ float Ins[10][18][25];
    __shared__ float Ws2[RCH*RCH*9];
    int t  = threadIdx.x;
    int b  = blockIdx.z;
    int h0 = blockIdx.y * 8;
    int w0 = blockIdx.x * 16;

    for (int e = t; e < RCH*RCH*9; e += 256) Ws2[e] = w[e];
    for (int e = t; e < 10*18*RCH; e += 256) {
        int ci  = e % RCH;
        int col = (e / RCH) % 18;
        int row = e / (RCH*18);
        int hh  = h0 + row - 1, wc = w0 + col - 1;
        float v = 0.f;
        if (hh >= 0 && hh < HH && wc >= 0 && wc < WW_)
            v = y1[(((size_t)b*HH + hh)*WW_ + wc)*RCH + ci];
        Ins[row][col][ci] = v;
    }
    __syncthreads();

    int pg  = t & 31;
    int py  = pg >> 2;
    int px0 = (pg & 3) << 2;
    int cg  = (t >> 5) * 3;
    float acc[4][3] = {};
#pragma unroll
    for (int kh = 0; kh < 3; kh++) {
#pragma unroll
        for (int kw = 0; kw < 3; kw++) {
            for (int ci = 0; ci < RCH; ci++) {
                float xv[4];
#pragma unroll
                for (int q = 0; q < 4; q++) xv[q] = Ins[py+kh][px0+q+kw][ci];
#pragma unroll
                for (int j = 0; j < 3; j++) {
                    float wv = Ws2[((cg+j)*RCH + ci)*9 + kh*3 + kw];
#pragma unroll
                    for (int q = 0; q < 4; q++) acc[q][j] += xv[q]*wv;
                }
            }
        }
    }
#pragma unroll
    for (int q = 0; q < 4; q++)
#pragma unroll
        for (int j = 0; j < 3; j++)
            y2[(((size_t)b*HH + h0+py)*WW_ + w0+px0+q)*RCH + cg+j]
                = acc[q][j] + bias[cg+j];
}

// ----------------- LCE conv 1x1 (24->192) + LeakyReLU + pool ----------------
__global__ void __launch_bounds__(256)
conv3_k(const float* __restrict__ y2, const float* __restrict__ w,
        const float* __restrict__ bias, float* __restrict__ y3,
        float* __restrict__ pool)
{
    __shared__ float Xs[32][25];
    __shared__ float Ws[CC*RCH];
    __shared__ float psum[CC];
    int t = threadIdx.x;
    size_t p0 = (size_t)blockIdx.x * 32;
    int b = (int)(p0 >> 16);

    for (int e = t; e < CC*RCH; e += 256) Ws[e] = w[e];
    for (int e = t; e < 32*RCH; e += 256) Xs[e/RCH][e%RCH] = y2[p0*RCH + e];
    if (t < CC) psum[t] = 0.f;
    __syncthreads();

    int pp = (t & 15) * 2;
    int cg = (t >> 4) * 12;
    float a0[12] = {}, a1[12] = {};
    for (int k = 0; k < RCH; k++) {
        float x0 = Xs[pp][k], x1 = Xs[pp+1][k];
#pragma unroll
        for (int j = 0; j < 12; j++) {
            float wv = Ws[(cg+j)*RCH + k];
            a0[j] += x0*wv; a1[j] += x1*wv;
        }
    }
#pragma unroll
    for (int j = 0; j < 12; j++) {
        int c = cg + j;
        float v0 = a0[j] + bias[c]; v0 = (v0 >= 0.f) ? v0 : 0.2f*v0;
        float v1 = a1[j] + bias[c]; v1 = (v1 >= 0.f) ? v1 : 0.2f*v1;
        y3[(p0+pp  )*CC + c] = v0;
        y3[(p0+pp+1)*CC + c] = v1;
        float v = v0 + v1;
        v += __shfl_xor_sync(~0u, v, 1);
        v += __shfl_xor_sync(~0u, v, 2);
        v += __shfl_xor_sync(~0u, v, 4);
        v += __shfl_xor_sync(~0u, v, 8);
        if ((t & 15) == 0) atomicAdd(&psum[c], v);
    }
    __syncthreads();
    if (t < CC) atomicAdd(&pool[b*CC + t], psum[t]);
}

// ------------------------------ SE gate ------------------------------------
__global__ void zero_pool_k(float* pool) { pool[threadIdx.x] = 0.f; }

__global__ void __launch_bounds__(192)
se_kernel(const float* __restrict__ pool, const float* __restrict__ fc1w,
          const float* __restrict__ fc2w, float* __restrict__ gate)
{
    __shared__ float ssh[CC];
    __shared__ float t1[RCH];
    int b = blockIdx.x;
    int t = threadIdx.x;
    ssh[t] = pool[b*CC + t] * (1.f / (float)LTOT);
    __syncthreads();
    if (t < RCH) {
        float a = 0.f;
        for (int c = 0; c < CC; c++) a += ssh[c]*fc1w[t*CC + c];
        t1[t] = fmaxf(a, 0.f);
    }
    __syncthreads();
    float a = 0.f;
#pragma unroll
    for (int j = 0; j < RCH; j++) a += t1[j]*fc2w[t*RCH + j];
    gate[b*CC + t] = 1.f / (1.f + __expf(-a));
}

// ------------------------------ launcher -----------------------------------
extern "C" void kernel_launch(void* const* d_in, const int* in_sizes, int n_in,
                              void* d_out, int out_size)
{
    const float* x       = (const float*)d_in[0];
    const float* n1g     = (const float*)d_in[1];
    const float* n1b     = (const float*)d_in[2];
    const float* qkv_w   = (const float*)d_in[3];
    const float* qkv_b   = (const float*)d_in[4];
    const float* rpb     = (const float*)d_in[5];
    const float* proj_w  = (const float*)d_in[6];
    const float* proj_b  = (const float*)d_in[7];
    const float* n2g     = (const float*)d_in[8];
    const float* n2b     = (const float*)d_in[9];
    const float* fc1_w   = (const float*)d_in[10];
    const float* fc1_b   = (const float*)d_in[11];
    const float* fc2_w   = (const float*)d_in[12];
    const float* fc2_b   = (const float*)d_in[13];
    const float* c1_w    = (const float*)d_in[14];
    const float* c1_b    = (const float*)d_in[15];
    const float* c2_w    = (const float*)d_in[16];
    const float* c2_b    = (const float*)d_in[17];
    const float* c3_w    = (const float*)d_in[18];
    const float* c3_b    = (const float*)d_in[19];
    const float* sefc1   = (const float*)d_in[20];
    const float* sefc2   = (const float*)d_in[21];
    float* out = (float*)d_out;

    float *xn, *qkv, *attn, *x1, *ln2, *hbuf, *y1, *y2, *y3, *pool, *gate;
    cudaGetSymbolAddress((void**)&xn,   g_xn);
    cudaGetSymbolAddress((void**)&qkv,  g_qkv);
    cudaGetSymbolAddress((void**)&attn, g_attn);
    cudaGetSymbolAddress((void**)&x1,   g_x1);
    cudaGetSymbolAddress((void**)&ln2,  g_ln2);
    cudaGetSymbolAddress((void**)&hbuf, g_h);
    cudaGetSymbolAddress((void**)&y1,   g_y1);
    cudaGetSymbolAddress((void**)&y2,   g_y2);
    cudaGetSymbolAddress((void**)&y3,   g_y3);
    cudaGetSymbolAddress((void**)&pool, g_pool);
    cudaGetSymbolAddress((void**)&gate, g_gate);

    // 1. LN1 -> xn
    ln_kernel<<<MROWS/4, dim3(32,4)>>>(x, n1g, n1b, xn);

    // 2. qkv GEMM: (131072 x 576) = xn @ qkv_w^T + b
    gemm_tc<0><<<dim3(576/64, MROWS/128), 256>>>(xn, qkv_w, qkv_b, qkv,
        MROWS, 3*CC, CC, nullptr, nullptr, nullptr);

    // 3. window attention (shift folded into gather/scatter)
    attn_kernel<<<BATCH*1024, 256>>>(qkv, rpb, attn);

    // 4. proj GEMM + residual(x) -> x1
    gemm_tc<1><<<dim3(CC/64, MROWS/128), 256>>>(attn, proj_w, proj_b, x1,
        MROWS, CC, CC, x, nullptr, nullptr);

    // 5. LN2 -> ln2
    ln_kernel<<<MROWS/4, dim3(32,4)>>>(x1, n2g, n2b, ln2);

    // 6. fc1 GEMM + exact GELU -> hbuf
    gemm_tc<2><<<dim3(HID/64, MROWS/128), 256>>>(ln2, fc1_w, fc1_b, hbuf,
        MROWS, HID, CC, nullptr, nullptr, nullptr);

    // 7-10. LCE branch on xn
    conv1_k<<<MROWS/32, 128>>>(xn, c1_w, c1_b, y1);
    conv2_k<<<dim3(WW_/16, HH/8, BATCH), 256>>>(y1, c2_w, c2_b, y2);
    zero_pool_k<<<1, BATCH*CC>>>(pool);
    conv3_k<<<MROWS/32, 256>>>(y2, c3_w, c3_b, y3, pool);
    se_kernel<<<BATCH, CC>>>(pool, sefc1, sefc2, gate);

    // 11. fc2 GEMM + x1 + y3*gate -> d_out
    gemm_tc<3><<<dim3(CC/64, MROWS/128), 256>>>(hbuf, fc2_w, fc2_b, out,
        MROWS, CC, HID, x1, y3, gate);
}

// round 10
// speedup vs baseline: 1.3753x; 1.0095x over previous
#include <cuda_runtime.h>
#include <cuda_bf16.h>
#include <math.h>

// ---------------------------------------------------------------------------
// SwinTransformerBlock (B=2, H=W=256, C=192, HID=768, heads=6, ws=8, shift=4)
// v5: tf32 mma.sync GEMMs with ldmatrix fragment loads (4x fewer LSU issues);
// fp32 fused window attention + LN + LCE convs unchanged.
// ---------------------------------------------------------------------------

#define BATCH   2
#define HH      256
#define WW_     256
#define CC      192
#define HID     768
#define NHEAD   6
#define HD      32
#define WS      8
#define NTOK    64          // ws*ws
#define LTOT    (HH*WW_)    // 65536
#define MROWS   (BATCH*LTOT) // 131072
#define RCH     24          // C/RED

// -------------------- scratch (device globals, no allocation) --------------
__device__ float g_xn  [(size_t)MROWS*CC];
__device__ float g_qkv [(size_t)MROWS*3*CC];
__device__ float g_attn[(size_t)MROWS*CC];
__device__ float g_x1  [(size_t)MROWS*CC];
__device__ float g_ln2 [(size_t)MROWS*CC];
__device__ float g_h   [(size_t)MROWS*HID];
__device__ float g_y1  [(size_t)MROWS*RCH];
__device__ float g_y2  [(size_t)MROWS*RCH];
__device__ float g_y3  [(size_t)MROWS*CC];
__device__ float g_pool[BATCH*CC];
__device__ float g_gate[BATCH*CC];

// ------------------------------ tf32 helpers --------------------------------
__device__ __forceinline__ unsigned f2tf(float f) {
    unsigned u;
    asm("cvt.rna.tf32.f32 %0, %1;" : "=r"(u) : "f"(f));
    return u;
}

// D(16x8,f32) += A(16x8,tf32,row) * B(8x8,tf32,col)
__device__ __forceinline__ void mma_tf32(float* c, const unsigned* a, const unsigned* b) {
    asm volatile(
        "mma.sync.aligned.m16n8k8.row.col.f32.tf32.tf32.f32 "
        "{%0,%1,%2,%3}, {%4,%5,%6,%7}, {%8,%9}, {%0,%1,%2,%3};\n"
        : "+f"(c[0]), "+f"(c[1]), "+f"(c[2]), "+f"(c[3])
        : "r"(a[0]), "r"(a[1]), "r"(a[2]), "r"(a[3]), "r"(b[0]), "r"(b[1]));
}

// warp-collective: load 4 8x8 b16 tiles (= one tf32 16x8 A-frag or 2 B-frags)
__device__ __forceinline__ void ldsm_x4(unsigned* r, unsigned saddr) {
    asm volatile("ldmatrix.sync.aligned.m8n8.x4.shared.b16 {%0,%1,%2,%3}, [%4];"
        : "=r"(r[0]), "=r"(r[1]), "=r"(r[2]), "=r"(r[3]) : "r"(saddr));
}

// -------------------------------- LayerNorm --------------------------------
__global__ void ln_kernel(const float* __restrict__ x, const float* __restrict__ g,
                          const float* __restrict__ b, float* __restrict__ o)
{
    int row  = blockIdx.x * 4 + threadIdx.y;
    int lane = threadIdx.x;
    const float* xr = x + (size_t)row * CC;
    float v[6];
    float s = 0.f;
#pragma unroll
    for (int k = 0; k < 6; k++) { v[k] = xr[lane + k*32]; s += v[k]; }
#pragma unroll
    for (int off = 16; off > 0; off >>= 1) s += __shfl_xor_sync(~0u, s, off);
    float mean = s * (1.f/192.f);
    float q = 0.f;
#pragma unroll
    for (int k = 0; k < 6; k++) { float d = v[k]-mean; q += d*d; }
#pragma unroll
    for (int off = 16; off > 0; off >>= 1) q += __shfl_xor_sync(~0u, q, off);
    float rs = rsqrtf(q * (1.f/192.f) + 1e-5f);
    float* orow = o + (size_t)row * CC;
#pragma unroll
    for (int k = 0; k < 6; k++) {
        int c = lane + k*32;
        orow[c] = (v[k]-mean)*rs*g[c] + b[c];
    }
}

// ------------------- tf32 tensor-core GEMM: out = X @ W^T -------------------
// X: (M,K) row-major, W: (N,K) row-major (= col-major KxN, matching mma .col).
// BM=128 BN=64 BK=16, 256 thr (8 warps), warp tile 32x32 = 2x4 m16n8k8 mmas.
// smem rows stride 20 words (LDSM row offsets hit distinct bank quads).
// Fragments via ldmatrix.x4.b16: tf32 16x8 A-frag == 4 b16 8x8 tiles.
// EPI 0: +bias | 1: +bias+res1 | 2: gelu(+bias) | 3: +bias+res1+res2*gate
__device__ __forceinline__ float gelu_exact(float x) {
    return 0.5f * x * (1.f + erff(x * 0.70710678118654752f));
}

template<int EPI>
__global__ void __launch_bounds__(256, 2)
gemm_tc(const float* __restrict__ X, const float* __restrict__ W,
        const float* __restrict__ bias, float* __restrict__ out,
        int M, int N, int K,
        const float* __restrict__ res1, const float* __restrict__ res2,
        const float* __restrict__ gate)
{
    __shared__ __align__(16) unsigned As[2][128][20];
    __shared__ __align__(16) unsigned Bs[2][64][20];

    int bm = blockIdx.y << 7;
    int bn = blockIdx.x << 6;
    int t    = threadIdx.x;
    int w    = t >> 5;
    int lane = t & 31;
    int g    = lane >> 2;       // groupID 0..7
    int tig  = lane & 3;        // thread-in-group 0..3
    int wm   = (w & 3) << 5;    // warp m offset: 0,32,64,96
    int wn   = (w >> 2) << 5;   // warp n offset: 0,32

    // ldmatrix per-lane source row/col within a fragment tile
    int arow = (lane & 7) + (lane & 8);          // A: lanes 8-15 -> +8 rows
    int acol = (lane & 16) ? 4 : 0;              // A: lanes 16-31 -> k+4
    int brow = (lane & 7) + ((lane & 16) >> 1);  // B: lanes 16-31 -> +8 rows
    int bcol = (lane & 8) ? 4 : 0;               // B: lanes 8-15 -> k+4
    unsigned asb = (unsigned)__cvta_generic_to_shared(&As[0][0][0]);
    unsigned bsb = (unsigned)__cvta_generic_to_shared(&Bs[0][0][0]);

    // cooperative staging addresses (same tile -> 2 A chunks + 1 B chunk)
    int sm0 = t >> 2;           // 0..63
    int sk4 = (t & 3) << 2;     // 0,4,8,12
    const float* Xg0 = X + (size_t)(bm + sm0)      * K + sk4;
    const float* Xg1 = X + (size_t)(bm + 64 + sm0) * K + sk4;
    const float* Wg  = W + (size_t)(bn + sm0)      * K + sk4;

    float acc[2][4][4];
#pragma unroll
    for (int i = 0; i < 2; i++)
#pragma unroll
        for (int j = 0; j < 4; j++)
#pragma unroll
            for (int q = 0; q < 4; q++) acc[i][j][q] = 0.f;

    int nt = K >> 4;

    // ---- prologue: stage tile 0 ----
    float4 rX0 = *reinterpret_cast<const float4*>(Xg0);
    float4 rX1 = *reinterpret_cast<const float4*>(Xg1);
    float4 rW  = *reinterpret_cast<const float4*>(Wg);
    *reinterpret_cast<uint4*>(&As[0][sm0][sk4]) =
        make_uint4(f2tf(rX0.x), f2tf(rX0.y), f2tf(rX0.z), f2tf(rX0.w));
    *reinterpret_cast<uint4*>(&As[0][64+sm0][sk4]) =
        make_uint4(f2tf(rX1.x), f2tf(rX1.y), f2tf(rX1.z), f2tf(rX1.w));
    *reinterpret_cast<uint4*>(&Bs[0][sm0][sk4]) =
        make_uint4(f2tf(rW.x), f2tf(rW.y), f2tf(rW.z), f2tf(rW.w));
    __syncthreads();

    for (int i = 0; i < nt; i++) {
        int cb = i & 1;
        if (i + 1 < nt) {           // prefetch next tile into registers
            int off = (i + 1) << 4;
            rX0 = *reinterpret_cast<const float4*>(Xg0 + off);
            rX1 = *reinterpret_cast<const float4*>(Xg1 + off);
            rW  = *reinterpret_cast<const float4*>(Wg  + off);
        }
#pragma unroll
        for (int s = 0; s < 2; s++) {
            int k0 = s << 3;
            unsigned a[2][4], b[2][4];
            ldsm_x4(a[0], asb + (((cb<<7) + wm      + arow)*20 + k0 + acol)*4u);
            ldsm_x4(a[1], asb + (((cb<<7) + wm + 16 + arow)*20 + k0 + acol)*4u);
            ldsm_x4(b[0], bsb + (((cb<<6) + wn      + brow)*20 + k0 + bcol)*4u);
            ldsm_x4(b[1], bsb + (((cb<<6) + wn + 16 + brow)*20 + k0 + bcol)*4u);
#pragma unroll
            for (int mi = 0; mi < 2; mi++) {
                mma_tf32(acc[mi][0], a[mi], &b[0][0]);
                mma_tf32(acc[mi][1], a[mi], &b[0][2]);
                mma_tf32(acc[mi][2], a[mi], &b[1][0]);
                mma_tf32(acc[mi][3], a[mi], &b[1][2]);
            }
        }
        if (i + 1 < nt) {           // stage next tile
            int nb = cb ^ 1;
            __syncthreads();        // prior reads of buf nb (tile i-1) done
            *reinterpret_cast<uint4*>(&As[nb][sm0][sk4]) =
                make_uint4(f2tf(rX0.x), f2tf(rX0.y), f2tf(rX0.z), f2tf(rX0.w));
            *reinterpret_cast<uint4*>(&As[nb][64+sm0][sk4]) =
                make_uint4(f2tf(rX1.x), f2tf(rX1.y), f2tf(rX1.z), f2tf(rX1.w));
            *reinterpret_cast<uint4*>(&Bs[nb][sm0][sk4]) =
                make_uint4(f2tf(rW.x), f2tf(rW.y), f2tf(rW.z), f2tf(rW.w));
            __syncthreads();
        }
    }

    // ---- epilogue ----
#pragma unroll
    for (int mi = 0; mi < 2; mi++) {
        int r0 = bm + wm + (mi << 4) + g;
        int r1 = r0 + 8;
        int batch = r0 >> 16;
#pragma unroll
        for (int ni = 0; ni < 4; ni++) {
            int c = bn + wn + (ni << 3) + (tig << 1);
            float b0 = __ldg(bias + c), b1 = __ldg(bias + c + 1);
            float v00 = acc[mi][ni][0] + b0, v01 = acc[mi][ni][1] + b1;
            float v10 = acc[mi][ni][2] + b0, v11 = acc[mi][ni][3] + b1;
            size_t o0 = (size_t)r0 * N + c;
            size_t o1 = (size_t)r1 * N + c;
            if (EPI == 1) {
                v00 += res1[o0]; v01 += res1[o0+1];
                v10 += res1[o1]; v11 += res1[o1+1];
            }
            if (EPI == 2) {
                v00 = gelu_exact(v00); v01 = gelu_exact(v01);
                v10 = gelu_exact(v10); v11 = gelu_exact(v11);
            }
            if (EPI == 3) {
                float g0 = gate[batch*CC + c], g1 = gate[batch*CC + c + 1];
                v00 += res1[o0]   + res2[o0]  *g0;
                v01 += res1[o0+1] + res2[o0+1]*g1;
                v10 += res1[o1]   + res2[o1]  *g0;
                v11 += res1[o1+1] + res2[o1+1]*g1;
            }
            *reinterpret_cast<float2*>(out + o0) = make_float2(v00, v01);
            *reinterpret_cast<float2*>(out + o1) = make_float2(v10, v11);
        }
    }
}

// ------------------------------- Attention ---------------------------------
// One block per (batch, window). Shift folded into gather/scatter indices:
// mask regions keyed on window coords (matching calculate_mask), data
// gathered/scattered at original coords (hs+4)&255.
__global__ void __launch_bounds__(256)
attn_kernel(const float* __restrict__ qkv, const float* __restrict__ rpb,
            float* __restrict__ out)
{
    __shared__ float qs[NTOK][33], ks[NTOK][33], vs[NTOK][33];
    __shared__ float S[NTOK][65];
    __shared__ int   rowi[NTOK];
    __shared__ int   regn[NTOK];

    int t   = threadIdx.x;
    int blk = blockIdx.x;
    int b   = blk >> 10;
    int wh  = (blk >> 5) & 31;
    int ww  = blk & 31;

    if (t < NTOK) {
        int i  = t >> 3, j = t & 7;
        int ha = wh*WS + i, wa = ww*WS + j;   // window (shifted-frame) coords
        rowi[t] = b*LTOT + ((ha+4)&255)*WW_ + ((wa+4)&255);
        int rh = (ha < 248) ? 0 : (ha < 252 ? 1 : 2);
        int rw = (wa < 248) ? 0 : (wa < 252 ? 1 : 2);
        regn[t] = rh*3 + rw;
    }
    __syncthreads();

    const float scale = 0.17677669529663687f; // 1/sqrt(32)

    for (int h = 0; h < NHEAD; h++) {
        {
            int tok  = t >> 2, part = t & 3;
            size_t base = (size_t)rowi[tok]*(3*CC) + h*HD + part*8;
            float4 q0 = *reinterpret_cast<const float4*>(qkv + base);
            float4 q1 = *reinterpret_cast<const float4*>(qkv + base + 4);
            float4 k0 = *reinterpret_cast<const float4*>(qkv + base + CC);
            float4 k1 = *reinterpret_cast<const float4*>(qkv + base + CC + 4);
            float4 v0 = *reinterpret_cast<const float4*>(qkv + base + 2*CC);
            float4 v1 = *reinterpret_cast<const float4*>(qkv + base + 2*CC + 4);
            int d = part*8;
            qs[tok][d+0]=q0.x; qs[tok][d+1]=q0.y; qs[tok][d+2]=q0.z; qs[tok][d+3]=q0.w;
            qs[tok][d+4]=q1.x; qs[tok][d+5]=q1.y; qs[tok][d+6]=q1.z; qs[tok][d+7]=q1.w;
            ks[tok][d+0]=k0.x; ks[tok][d+1]=k0.y; ks[tok][d+2]=k0.z; ks[tok][d+3]=k0.w;
            ks[tok][d+4]=k1.x; ks[tok][d+5]=k1.y; ks[tok][d+6]=k1.z; ks[tok][d+7]=k1.w;
            vs[tok][d+0]=v0.x; vs[tok][d+1]=v0.y; vs[tok][d+2]=v0.z; vs[tok][d+3]=v0.w;
            vs[tok][d+4]=v1.x; vs[tok][d+5]=v1.y; vs[tok][d+6]=v1.z; vs[tok][d+7]=v1.w;
        }
        __syncthreads();

        {
            int i0 = (t >> 4) << 2;
            int j0 = (t & 15) << 2;
            float sacc[4][4] = {};
#pragma unroll
            for (int d = 0; d < HD; d++) {
                float a[4], bb[4];
#pragma unroll
                for (int ii = 0; ii < 4; ii++) a[ii]  = qs[i0+ii][d];
#pragma unroll
                for (int jj = 0; jj < 4; jj++) bb[jj] = ks[j0+jj][d];
#pragma unroll
                for (int ii = 0; ii < 4; ii++)
#pragma unroll
                    for (int jj = 0; jj < 4; jj++)
                        sacc[ii][jj] += a[ii]*bb[jj];
            }
#pragma unroll
            for (int ii = 0; ii < 4; ii++) {
#pragma unroll
                for (int jj = 0; jj < 4; jj++) {
                    int i = i0+ii, j = j0+jj;
                    int rel = ((i>>3)-(j>>3)+7)*15 + ((i&7)-(j&7)+7);
                    float bias = __ldg(rpb + rel*NHEAD + h);
                    float mv   = (regn[i] == regn[j]) ? 0.f : -100.f;
                    S[i][j] = sacc[ii][jj]*scale + bias + mv;
                }
            }
        }
        __syncthreads();

        {
            int ri = t >> 2;
            int c0 = (t & 3) << 4;
            float mx = -1e30f;
#pragma unroll
            for (int cc = 0; cc < 16; cc++) mx = fmaxf(mx, S[ri][c0+cc]);
            mx = fmaxf(mx, __shfl_xor_sync(~0u, mx, 1));
            mx = fmaxf(mx, __shfl_xor_sync(~0u, mx, 2));
            float ev[16];
            float sum = 0.f;
#pragma unroll
            for (int cc = 0; cc < 16; cc++) {
                ev[cc] = __expf(S[ri][c0+cc] - mx);
                sum += ev[cc];
            }
            sum += __shfl_xor_sync(~0u, sum, 1);
            sum += __shfl_xor_sync(~0u, sum, 2);
            float inv = 1.f / sum;
#pragma unroll
            for (int cc = 0; cc < 16; cc++) S[ri][c0+cc] = ev[cc]*inv;
        }
        __syncthreads();

        {
            int r0 = (t >> 3) << 1;
            int d0 = (t & 7) << 2;
            float o0[4] = {}, o1[4] = {};
#pragma unroll
            for (int j = 0; j < NTOK; j++) {
                float p0 = S[r0][j], p1 = S[r0+1][j];
#pragma unroll
                for (int dd = 0; dd < 4; dd++) {
                    float vv = vs[j][d0+dd];
                    o0[dd] += p0*vv;
                    o1[dd] += p1*vv;
                }
            }
            size_t ob0 = (size_t)rowi[r0  ]*CC + h*HD + d0;
            size_t ob1 = (size_t)rowi[r0+1]*CC + h*HD + d0;
            *reinterpret_cast<float4*>(out + ob0) = make_float4(o0[0],o0[1],o0[2],o0[3]);
            *reinterpret_cast<float4*>(out + ob1) = make_float4(o1[0],o1[1],o1[2],o1[3]);
        }
        __syncthreads();
    }
}

// ------------------------------ LCE conv 1x1 (192->24) ---------------------
__global__ void __launch_bounds__(128)
conv1_k(const float* __restrict__ xin, const float* __restrict__ w,
        const float* __restrict__ bias, float* __restrict__ y)
{
    __shared__ float Xs[32][193];
    __shared__ float Ws[RCH*CC];
    int t = threadIdx.x;
    size_t p0 = (size_t)blockIdx.x * 32;

    for (int e = t; e < RCH*CC; e += 128) Ws[e] = w[e];
    for (int e = t; e < 32*CC; e += 128) {
        int p = e / CC, c = e % CC;
        Xs[p][c] = xin[(p0+p)*CC + c];
    }
    __syncthreads();

    int pp = (t & 15) * 2;
    int cg = (t >> 4) * 3;
    float a0[3] = {}, a1[3] = {};
    for (int k = 0; k < CC; k++) {
        float x0 = Xs[pp][k], x1 = Xs[pp+1][k];
#pragma unroll
        for (int j = 0; j < 3; j++) {
            float wv = Ws[(cg+j)*CC + k];
            a0[j] += x0*wv; a1[j] += x1*wv;
        }
    }
#pragma unroll
    for (int j = 0; j < 3; j++) {
        int c = cg+j;
        y[(p0+pp  )*RCH + c] = a0[j] + bias[c];
        y[(p0+pp+1)*RCH + c] = a1[j] + bias[c];
    }
}

// ------------------------------ LCE conv 3x3 (24->24, pad 1) ----------------
__global__ void __launch_bounds__(256)
conv2_k(const float* __restrict__ y1, const float* __restrict__ w,
        const float* __restrict__ bias, float* __restrict__ y2)
{
    __shared__ float Ins[10][18][25];
    __shared__ float Ws2[RCH*RCH*9];
    int t  = threadIdx.x;
    int b  = blockIdx.z;
    int h0 = blockIdx.y * 8;
    int w0 = blockIdx.x * 16;

    for (int e = t; e < RCH*RCH*9; e += 256) Ws2[e] = w[e];
    for (int e = t; e < 10*18*RCH; e += 256) {
        int ci  = e % RCH;
        int col = (e / RCH) % 18;
        int row = e / (RCH*18);
        int hh  = h0 + row - 1, wc = w0 + col - 1;
        float v = 0.f;
        if (hh >= 0 && hh < HH && wc >= 0 && wc < WW_)
            v = y1[(((size_t)b*HH + hh)*WW_ + wc)*RCH + ci];
        Ins[row][col][ci] = v;
    }
    __syncthreads();

    int pg  = t & 31;
    int py  = pg >> 2;
    int px0 = (pg & 3) << 2;
    int cg  = (t >> 5) * 3;
    float acc[4][3] = {};
#pragma unroll
    for (int kh = 0; kh < 3; kh++) {
#pragma unroll
        for (int kw = 0; kw < 3; kw++) {
            for (int ci = 0; ci < RCH; ci++) {
                float xv[4];
#pragma unroll
                for (int q = 0; q < 4; q++) xv[q] = Ins[py+kh][px0+q+kw][ci];
#pragma unroll
                for (int j = 0; j < 3; j++) {
                    float wv = Ws2[((cg+j)*RCH + ci)*9 + kh*3 + kw];
#pragma unroll
                    for (int q = 0; q < 4; q++) acc[q][j] += xv[q]*wv;
                }
            }
        }
    }
#pragma unroll
    for (int q = 0; q < 4; q++)
#pragma unroll
        for (int j = 0; j < 3; j++)
            y2[(((size_t)b*HH + h0+py)*WW_ + w0+px0+q)*RCH + cg+j]
                = acc[q][j] + bias[cg+j];
}

// ----------------- LCE conv 1x1 (24->192) + LeakyReLU + pool ----------------
__global__ void __launch_bounds__(256)
conv3_k(const float* __restrict__ y2, const float* __restrict__ w,
        const float* __restrict__ bias, float* __restrict__ y3,
        float* __restrict__ pool)
{
    __shared__ float Xs[32][25];
    __shared__ float Ws[CC*RCH];
    __shared__ float psum[CC];
    int t = threadIdx.x;
    size_t p0 = (size_t)blockIdx.x * 32;
    int b = (int)(p0 >> 16);

    for (int e = t; e < CC*RCH; e += 256) Ws[e] = w[e];
    for (int e = t; e < 32*RCH; e += 256) Xs[e/RCH][e%RCH] = y2[p0*RCH + e];
    if (t < CC) psum[t] = 0.f;
    __syncthreads();

    int pp = (t & 15) * 2;
    int cg = (t >> 4) * 12;
    float a0[12] = {}, a1[12] = {};
    for (int k = 0; k < RCH; k++) {
        float x0 = Xs[pp][k], x1 = Xs[pp+1][k];
#pragma unroll
        for (int j = 0; j < 12; j++) {
            float wv = Ws[(cg+j)*RCH + k];
            a0[j] += x0*wv; a1[j] += x1*wv;
        }
    }
#pragma unroll
    for (int j = 0; j < 12; j++) {
        int c = cg + j;
        float v0 = a0[j] + bias[c]; v0 = (v0 >= 0.f) ? v0 : 0.2f*v0;
        float v1 = a1[j] + bias[c]; v1 = (v1 >= 0.f) ? v1 : 0.2f*v1;
        y3[(p0+pp  )*CC + c] = v0;
        y3[(p0+pp+1)*CC + c] = v1;
        float v = v0 + v1;
        v += __shfl_xor_sync(~0u, v, 1);
        v += __shfl_xor_sync(~0u, v, 2);
        v += __shfl_xor_sync(~0u, v, 4);
        v += __shfl_xor_sync(~0u, v, 8);
        if ((t & 15) == 0) atomicAdd(&psum[c], v);
    }
    __syncthreads();
    if (t < CC) atomicAdd(&pool[b*CC + t], psum[t]);
}

// ------------------------------ SE gate ------------------------------------
__global__ void zero_pool_k(float* pool) { pool[threadIdx.x] = 0.f; }

__global__ void __launch_bounds__(192)
se_kernel(const float* __restrict__ pool, const float* __restrict__ fc1w,
          const float* __restrict__ fc2w, float* __restrict__ gate)
{
    __shared__ float ssh[CC];
    __shared__ float t1[RCH];
    int b = blockIdx.x;
    int t = threadIdx.x;
    ssh[t] = pool[b*CC + t] * (1.f / (float)LTOT);
    __syncthreads();
    if (t < RCH) {
        float a = 0.f;
        for (int c = 0; c < CC; c++) a += ssh[c]*fc1w[t*CC + c];
        t1[t] = fmaxf(a, 0.f);
    }
    __syncthreads();
    float a = 0.f;
#pragma unroll
    for (int j = 0; j < RCH; j++) a += t1[j]*fc2w[t*RCH + j];
    gate[b*CC + t] = 1.f / (1.f + __expf(-a));
}

// ------------------------------ launcher -----------------------------------
extern "C" void kernel_launch(void* const* d_in, const int* in_sizes, int n_in,
                              void* d_out, int out_size)
{
    const float* x       = (const float*)d_in[0];
    const float* n1g     = (const float*)d_in[1];
    const float* n1b     = (const float*)d_in[2];
    const float* qkv_w   = (const float*)d_in[3];
    const float* qkv_b   = (const float*)d_in[4];
    const float* rpb     = (const float*)d_in[5];
    const float* proj_w  = (const float*)d_in[6];
    const float* proj_b  = (const float*)d_in[7];
    const float* n2g     = (const float*)d_in[8];
    const float* n2b     = (const float*)d_in[9];
    const float* fc1_w   = (const float*)d_in[10];
    const float* fc1_b   = (const float*)d_in[11];
    const float* fc2_w   = (const float*)d_in[12];
    const float* fc2_b   = (const float*)d_in[13];
    const float* c1_w    = (const float*)d_in[14];
    const float* c1_b    = (const float*)d_in[15];
    const float* c2_w    = (const float*)d_in[16];
    const float* c2_b    = (const float*)d_in[17];
    const float* c3_w    = (const float*)d_in[18];
    const float* c3_b    = (const float*)d_in[19];
    const float* sefc1   = (const float*)d_in[20];
    const float* sefc2   = (const float*)d_in[21];
    float* out = (float*)d_out;

    float *xn, *qkv, *attn, *x1, *ln2, *hbuf, *y1, *y2, *y3, *pool, *gate;
    cudaGetSymbolAddress((void**)&xn,   g_xn);
    cudaGetSymbolAddress((void**)&qkv,  g_qkv);
    cudaGetSymbolAddress((void**)&attn, g_attn);
    cudaGetSymbolAddress((void**)&x1,   g_x1);
    cudaGetSymbolAddress((void**)&ln2,  g_ln2);
    cudaGetSymbolAddress((void**)&hbuf, g_h);
    cudaGetSymbolAddress((void**)&y1,   g_y1);
    cudaGetSymbolAddress((void**)&y2,   g_y2);
    cudaGetSymbolAddress((void**)&y3,   g_y3);
    cudaGetSymbolAddress((void**)&pool, g_pool);
    cudaGetSymbolAddress((void**)&gate, g_gate);

    // 1. LN1 -> xn
    ln_kernel<<<MROWS/4, dim3(32,4)>>>(x, n1g, n1b, xn);

    // 2. qkv GEMM: (131072 x 576) = xn @ qkv_w^T + b
    gemm_tc<0><<<dim3(576/64, MROWS/128), 256>>>(xn, qkv_w, qkv_b, qkv,
        MROWS, 3*CC, CC, nullptr, nullptr, nullptr);

    // 3. window attention (shift folded into gather/scatter)
    attn_kernel<<<BATCH*1024, 256>>>(qkv, rpb, attn);

    // 4. proj GEMM + residual(x) -> x1
    gemm_tc<1><<<dim3(CC/64, MROWS/128), 256>>>(attn, proj_w, proj_b, x1,
        MROWS, CC, CC, x, nullptr, nullptr);

    // 5. LN2 -> ln2
    ln_kernel<<<MROWS/4, dim3(32,4)>>>(x1, n2g, n2b, ln2);

    // 6. fc1 GEMM + exact GELU -> hbuf
    gemm_tc<2><<<dim3(HID/64, MROWS/128), 256>>>(ln2, fc1_w, fc1_b, hbuf,
        MROWS, HID, CC, nullptr, nullptr, nullptr);

    // 7-10. LCE branch on xn
    conv1_k<<<MROWS/32, 128>>>(xn, c1_w, c1_b, y1);
    conv2_k<<<dim3(WW_/16, HH/8, BATCH), 256>>>(y1, c2_w, c2_b, y2);
    zero_pool_k<<<1, BATCH*CC>>>(pool);
    conv3_k<<<MROWS/32, 256>>>(y2, c3_w, c3_b, y3, pool);
    se_kernel<<<BATCH, CC>>>(pool, sefc1, sefc2, gate);

    // 11. fc2 GEMM + x1 + y3*gate -> d_out
    gemm_tc<3><<<dim3(CC/64, MROWS/128), 256>>>(hbuf, fc2_w, fc2_b, out,
        MROWS, CC, HID, x1, y3, gate);
}